// round 4
// baseline (speedup 1.0000x reference)
#include <cuda_runtime.h>
#include <cuda_bf16.h>

#define N_NODES 100000
#define N_EDGES 1600000
#define NFEAT   128
#define NCLASS  40
#define BN_EPS  1e-5f

// ---------------- scratch (static device globals; no allocation) ----------------
__device__ int   g_deg[N_NODES];
__device__ int   g_off[N_NODES];
__device__ int   g_cur[N_NODES];
__device__ float g_inv[N_NODES];
__device__ int   g_csr[N_EDGES];
__device__ int   g_bsums[128];
__device__ int   g_is64;

__device__ float g_mean[(size_t)N_NODES * NFEAT];
__device__ float g_h1[(size_t)N_NODES * NFEAT];
__device__ float g_h2[(size_t)N_NODES * NFEAT];

__device__ float g_bnsum[NFEAT];
__device__ float g_bnsq[NFEAT];
__device__ float g_bnscale[NFEAT];
__device__ float g_bnshift[NFEAT];

// ---------------- setup: dtype detect + degree zero (fused) ----------------
__global__ void setup_kernel(const int* __restrict__ ei32) {
    int i = blockIdx.x * blockDim.x + threadIdx.x;
    if (i < N_NODES) g_deg[i] = 0;
    // block 0 additionally probes the edge dtype:
    // int64 => every odd int32 word (high word) is 0 (all values < 1e5).
    // int32 => odd words are random node ids; 1024 consecutive zeros ~ impossible.
    if (blockIdx.x == 0) {
        __shared__ int any;
        if (threadIdx.x == 0) any = 0;
        __syncthreads();
        int nz = 0;
        for (int t = threadIdx.x; t < 1024; t += blockDim.x)
            if (ei32[2 * t + 1] != 0) nz = 1;
        if (nz) atomicOr(&any, 1);
        __syncthreads();
        if (threadIdx.x == 0) g_is64 = any ? 0 : 1;
    }
}

__device__ __forceinline__ int edge_elem(const int* __restrict__ ei32, int idx) {
    return g_is64 ? ei32[2 * idx] : ei32[idx];
}

// ---------------- CSR build ----------------
__global__ void hist_kernel(const int* __restrict__ ei32) {
    int e = blockIdx.x * blockDim.x + threadIdx.x;
    if (e < N_EDGES) {
        int d = edge_elem(ei32, N_EDGES + e);
        atomicAdd(&g_deg[d], 1);
    }
}

__global__ void scan1_kernel() {
    __shared__ int s[1024];
    int i = blockIdx.x * 1024 + threadIdx.x;
    int v = (i < N_NODES) ? g_deg[i] : 0;
    s[threadIdx.x] = v;
    __syncthreads();
    for (int off = 1; off < 1024; off <<= 1) {
        int t = (threadIdx.x >= off) ? s[threadIdx.x - off] : 0;
        __syncthreads();
        s[threadIdx.x] += t;
        __syncthreads();
    }
    if (i < N_NODES) g_off[i] = s[threadIdx.x] - v;   // exclusive within block
    if (threadIdx.x == 1023) g_bsums[blockIdx.x] = s[1023];
}

__global__ void scan2_kernel(int nblocks) {
    __shared__ int s[128];
    int t = threadIdx.x;
    int v = (t < nblocks) ? g_bsums[t] : 0;
    s[t] = v;
    __syncthreads();
    for (int off = 1; off < 128; off <<= 1) {
        int u = (t >= off) ? s[t - off] : 0;
        __syncthreads();
        s[t] += u;
        __syncthreads();
    }
    if (t < nblocks) g_bsums[t] = s[t] - v;           // exclusive over blocks
}

__global__ void scan3_kernel() {
    int i = blockIdx.x * blockDim.x + threadIdx.x;
    if (i < N_NODES) {
        int o = g_off[i] + g_bsums[i >> 10];
        g_off[i] = o;
        g_cur[i] = o;
        int d = g_deg[i];
        g_inv[i] = 1.0f / (float)(d > 1 ? d : 1);
    }
}

__global__ void scatter_kernel(const int* __restrict__ ei32) {
    int e = blockIdx.x * blockDim.x + threadIdx.x;
    if (e < N_EDGES) {
        int s = edge_elem(ei32, e);
        int d = edge_elem(ei32, N_EDGES + e);
        int p = atomicAdd(&g_cur[d], 1);
        g_csr[p] = s;
    }
}

// ---------------- aggregation: warp per node, float4 lanes ----------------
__global__ void agg_kernel(const float* __restrict__ X, float* __restrict__ out) {
    int warp = (blockIdx.x * blockDim.x + threadIdx.x) >> 5;
    if (warp >= N_NODES) return;
    int lane = threadIdx.x & 31;
    int beg = g_off[warp];
    int cnt = g_deg[warp];
    const float4* __restrict__ Xv = (const float4*)X;

    float4 a0 = make_float4(0.f, 0.f, 0.f, 0.f);
    float4 a1 = a0, a2 = a0, a3 = a0;

    int i = 0;
    for (; i + 4 <= cnt; i += 4) {
        int s0 = g_csr[beg + i + 0];
        int s1 = g_csr[beg + i + 1];
        int s2 = g_csr[beg + i + 2];
        int s3 = g_csr[beg + i + 3];
        float4 v0 = Xv[s0 * 32 + lane];
        float4 v1 = Xv[s1 * 32 + lane];
        float4 v2 = Xv[s2 * 32 + lane];
        float4 v3 = Xv[s3 * 32 + lane];
        a0.x += v0.x; a0.y += v0.y; a0.z += v0.z; a0.w += v0.w;
        a1.x += v1.x; a1.y += v1.y; a1.z += v1.z; a1.w += v1.w;
        a2.x += v2.x; a2.y += v2.y; a2.z += v2.z; a2.w += v2.w;
        a3.x += v3.x; a3.y += v3.y; a3.z += v3.z; a3.w += v3.w;
    }
    for (; i < cnt; i++) {
        int s0 = g_csr[beg + i];
        float4 v0 = Xv[s0 * 32 + lane];
        a0.x += v0.x; a0.y += v0.y; a0.z += v0.z; a0.w += v0.w;
    }
    float inv = g_inv[warp];
    float4 r;
    r.x = (a0.x + a1.x + a2.x + a3.x) * inv;
    r.y = (a0.y + a1.y + a2.y + a3.y) * inv;
    r.z = (a0.z + a1.z + a2.z + a3.z) * inv;
    r.w = (a0.w + a1.w + a2.w + a3.w) * inv;
    ((float4*)out)[warp * 32 + lane] = r;
}

// ---------------- fused dual-source GEMM: H = Am@Wl^T + Ax@Wr^T + b ----------------
// Fo=128: BM=128, BN=128, BK=16, 256 threads, 8x8 register tile, float4 smem reads.
template <bool RELU>
__global__ void __launch_bounds__(256)
gemm128_kernel(const float* __restrict__ Am, const float* __restrict__ Ax,
               const float* __restrict__ Wl, const float* __restrict__ Wr,
               const float* __restrict__ bias, float* __restrict__ out) {
    __shared__ float As[16][136];   // [k][row]; stride 136 keeps float4 alignment
    __shared__ float Bs[16][136];   // [k][col]

    int tid = threadIdx.x;
    int tx = tid & 15;              // cols tx*4 + {0..3}, + 64
    int ty = tid >> 4;              // rows ty*4 + {0..3}, + 64
    int rowBase = blockIdx.x * 128;

    int lrow = tid >> 1;            // 0..127 (tile row / weight out-idx)
    int lk   = (tid & 1) * 8;       // 0 or 8

    float acc[8][8];
#pragma unroll
    for (int i = 0; i < 8; i++)
#pragma unroll
        for (int j = 0; j < 8; j++) acc[i][j] = 0.f;

    for (int c = 0; c < 16; c++) {
        const float* A = (c < 8) ? Am : Ax;
        const float* W = (c < 8) ? Wl : Wr;
        int ko = (c & 7) * 16;

        // stage global -> regs (8 A elems + 8 W elems per thread)
        float4 a0, a1;
        int g = rowBase + lrow;
        if (g < N_NODES) {
            const float4* p = (const float4*)(A + (size_t)g * 128 + ko + lk);
            a0 = p[0]; a1 = p[1];
        } else {
            a0 = make_float4(0.f, 0.f, 0.f, 0.f); a1 = a0;
        }
        const float4* q = (const float4*)(W + lrow * 128 + ko + lk);
        float4 b0 = q[0], b1 = q[1];

        __syncthreads();            // previous-iter readers done
        As[lk + 0][lrow] = a0.x; As[lk + 1][lrow] = a0.y;
        As[lk + 2][lrow] = a0.z; As[lk + 3][lrow] = a0.w;
        As[lk + 4][lrow] = a1.x; As[lk + 5][lrow] = a1.y;
        As[lk + 6][lrow] = a1.z; As[lk + 7][lrow] = a1.w;
        Bs[lk + 0][lrow] = b0.x; Bs[lk + 1][lrow] = b0.y;
        Bs[lk + 2][lrow] = b0.z; Bs[lk + 3][lrow] = b0.w;
        Bs[lk + 4][lrow] = b1.x; Bs[lk + 5][lrow] = b1.y;
        Bs[lk + 6][lrow] = b1.z; Bs[lk + 7][lrow] = b1.w;
        __syncthreads();

#pragma unroll
        for (int kk = 0; kk < 16; kk++) {
            float4 av0 = *(const float4*)&As[kk][ty * 4];
            float4 av1 = *(const float4*)&As[kk][ty * 4 + 64];
            float4 bv0 = *(const float4*)&Bs[kk][tx * 4];
            float4 bv1 = *(const float4*)&Bs[kk][tx * 4 + 64];
            float a[8] = {av0.x, av0.y, av0.z, av0.w, av1.x, av1.y, av1.z, av1.w};
            float b[8] = {bv0.x, bv0.y, bv0.z, bv0.w, bv1.x, bv1.y, bv1.z, bv1.w};
#pragma unroll
            for (int i = 0; i < 8; i++)
#pragma unroll
                for (int j = 0; j < 8; j++) acc[i][j] += a[i] * b[j];
        }
    }

    // epilogue: rows rowBase + ty*4+{0..3} (+64), cols tx*4+{0..3} (+64)
    float bl0[4], bl1[4];
#pragma unroll
    for (int j = 0; j < 4; j++) {
        bl0[j] = __ldg(&bias[tx * 4 + j]);
        bl1[j] = __ldg(&bias[tx * 4 + 64 + j]);
    }
#pragma unroll
    for (int i = 0; i < 8; i++) {
        int g = rowBase + ty * 4 + (i & 3) + (i >> 2) * 64;
        if (g < N_NODES) {
            float4 v0, v1;
            v0.x = acc[i][0] + bl0[0]; v0.y = acc[i][1] + bl0[1];
            v0.z = acc[i][2] + bl0[2]; v0.w = acc[i][3] + bl0[3];
            v1.x = acc[i][4] + bl1[0]; v1.y = acc[i][5] + bl1[1];
            v1.z = acc[i][6] + bl1[2]; v1.w = acc[i][7] + bl1[3];
            if (RELU) {
                v0.x = fmaxf(v0.x, 0.f); v0.y = fmaxf(v0.y, 0.f);
                v0.z = fmaxf(v0.z, 0.f); v0.w = fmaxf(v0.w, 0.f);
                v1.x = fmaxf(v1.x, 0.f); v1.y = fmaxf(v1.y, 0.f);
                v1.z = fmaxf(v1.z, 0.f); v1.w = fmaxf(v1.w, 0.f);
            }
            *(float4*)(out + (size_t)g * 128 + tx * 4) = v0;
            *(float4*)(out + (size_t)g * 128 + tx * 4 + 64) = v1;
        }
    }
}

// Fo = 40 version: BM=64, BN=40, BK=32, 128 threads, 4x5 register tile.
__global__ void gemm40_kernel(const float* __restrict__ Am, const float* __restrict__ Ax,
                              const float* __restrict__ Wl, const float* __restrict__ Wr,
                              const float* __restrict__ bias, float* __restrict__ out) {
    __shared__ float As[32][65];
    __shared__ float Bs[40][33];

    int tid = threadIdx.x;
    int tx = tid & 7;               // cols tx + 8*j, j<5
    int ty = tid >> 3;              // rows ty + 16*i, i<4
    int rowBase = blockIdx.x * 64;

    float acc[4][5];
#pragma unroll
    for (int i = 0; i < 4; i++)
#pragma unroll
        for (int j = 0; j < 5; j++) acc[i][j] = 0.f;

    for (int c = 0; c < 8; c++) {
        const float* A = (c < 4) ? Am : Ax;
        const float* W = (c < 4) ? Wl : Wr;
        int ko = (c & 3) * 32;

#pragma unroll
        for (int p = 0; p < 16; p++) {
            int idx = tid + p * 128;
            int row = idx >> 5, kk = idx & 31;
            int g = rowBase + row;
            As[kk][row] = (g < N_NODES) ? A[(size_t)g * 128 + ko + kk] : 0.f;
        }
#pragma unroll
        for (int p = 0; p < 10; p++) {
            int idx = tid + p * 128;
            if (idx < 40 * 32) {
                int o = idx >> 5, kk = idx & 31;
                Bs[o][kk] = W[o * 128 + ko + kk];
            }
        }
        __syncthreads();

#pragma unroll
        for (int kk = 0; kk < 32; kk++) {
            float a[4], b[5];
#pragma unroll
            for (int i = 0; i < 4; i++) a[i] = As[kk][ty + 16 * i];
#pragma unroll
            for (int j = 0; j < 5; j++) b[j] = Bs[tx + 8 * j][kk];
#pragma unroll
            for (int i = 0; i < 4; i++)
#pragma unroll
                for (int j = 0; j < 5; j++) acc[i][j] += a[i] * b[j];
        }
        __syncthreads();
    }

#pragma unroll
    for (int i = 0; i < 4; i++) {
        int g = rowBase + ty + 16 * i;
        if (g < N_NODES) {
#pragma unroll
            for (int j = 0; j < 5; j++) {
                int o = tx + 8 * j;
                out[(size_t)g * 40 + o] = acc[i][j] + __ldg(&bias[o]);
            }
        }
    }
}

// ---------------- batch norm ----------------
__global__ void zero_bn_kernel() {
    int t = threadIdx.x;
    if (t < NFEAT) { g_bnsum[t] = 0.f; g_bnsq[t] = 0.f; }
}

// F must be a multiple of 4; each thread owns 4 adjacent columns (float4 loads).
template <int F>
__global__ void bn_stats_kernel(const float* __restrict__ X, int rowsPerBlock) {
    int c4 = threadIdx.x;           // float4 column index
    if (c4 >= F / 4) return;
    int r0 = blockIdx.x * rowsPerBlock;
    int r1 = r0 + rowsPerBlock;
    if (r1 > N_NODES) r1 = N_NODES;
    const float4* Xv = (const float4*)X;
    float4 s = make_float4(0.f, 0.f, 0.f, 0.f);
    float4 q = make_float4(0.f, 0.f, 0.f, 0.f);
    for (int r = r0; r < r1; r++) {
        float4 v = Xv[(size_t)r * (F / 4) + c4];
        s.x += v.x; s.y += v.y; s.z += v.z; s.w += v.w;
        q.x += v.x * v.x; q.y += v.y * v.y; q.z += v.z * v.z; q.w += v.w * v.w;
    }
    atomicAdd(&g_bnsum[c4 * 4 + 0], s.x);
    atomicAdd(&g_bnsum[c4 * 4 + 1], s.y);
    atomicAdd(&g_bnsum[c4 * 4 + 2], s.z);
    atomicAdd(&g_bnsum[c4 * 4 + 3], s.w);
    atomicAdd(&g_bnsq[c4 * 4 + 0], q.x);
    atomicAdd(&g_bnsq[c4 * 4 + 1], q.y);
    atomicAdd(&g_bnsq[c4 * 4 + 2], q.z);
    atomicAdd(&g_bnsq[c4 * 4 + 3], q.w);
}

template <int F>
__global__ void bn_final_kernel(const float* __restrict__ gamma, const float* __restrict__ beta) {
    int c = threadIdx.x;
    if (c >= F) return;
    float invN = 1.0f / (float)N_NODES;
    float mu = g_bnsum[c] * invN;
    float var = g_bnsq[c] * invN - mu * mu;
    var = fmaxf(var, 0.f);
    float sc = gamma[c] * rsqrtf(var + BN_EPS);
    g_bnscale[c] = sc;
    g_bnshift[c] = beta[c] - mu * sc;
}

template <int F, bool RELU>
__global__ void bn_apply_kernel(float* __restrict__ X) {
    long long i = (long long)blockIdx.x * blockDim.x + threadIdx.x;
    long long total = (long long)N_NODES * F;
    if (i < total) {
        int col = (int)(i % F);
        float v = X[i] * g_bnscale[col] + g_bnshift[col];
        if (RELU) v = fmaxf(v, 0.f);
        X[i] = v;
    }
}

// ---------------- launch ----------------
extern "C" void kernel_launch(void* const* d_in, const int* in_sizes, int n_in,
                              void* d_out, int out_size) {
    const float* x    = (const float*)d_in[0];
    const int*   ei32 = (const int*)  d_in[1];
    const float* W1l = (const float*)d_in[2];
    const float* b1  = (const float*)d_in[3];
    const float* W1r = (const float*)d_in[4];
    const float* Wxl = (const float*)d_in[5];
    const float* bx  = (const float*)d_in[6];
    const float* Wxr = (const float*)d_in[7];
    const float* W2l = (const float*)d_in[8];
    const float* b2  = (const float*)d_in[9];
    const float* W2r = (const float*)d_in[10];
    const float* g3  = (const float*)d_in[11];
    const float* be3 = (const float*)d_in[12];
    const float* g2  = (const float*)d_in[13];
    const float* be2 = (const float*)d_in[14];
    float* out = (float*)d_out;

    float* mean = nullptr; float* h1 = nullptr; float* h2 = nullptr;
    cudaGetSymbolAddress((void**)&mean, g_mean);
    cudaGetSymbolAddress((void**)&h1, g_h1);
    cudaGetSymbolAddress((void**)&h2, g_h2);

    const int NB_NODE = (N_NODES + 255) / 256;       // 391
    const int NB_EDGE = (N_EDGES + 255) / 256;       // 6250
    const int NB_SCAN = (N_NODES + 1023) / 1024;     // 98
    const int NB_AGG  = (N_NODES + 15) / 16;         // warp/node, 16 warps/block
    const int NB_G128 = (N_NODES + 127) / 128;       // 782
    const int NB_G40  = (N_NODES + 63) / 64;         // 1563
    const int BN_BLOCKS = 256;
    const int ROWS_PER_BLOCK = (N_NODES + BN_BLOCKS - 1) / BN_BLOCKS;

    // CSR build (once per launch)
    setup_kernel<<<NB_NODE, 256>>>(ei32);
    hist_kernel<<<NB_EDGE, 256>>>(ei32);
    scan1_kernel<<<NB_SCAN, 1024>>>();
    scan2_kernel<<<1, 128>>>(NB_SCAN);
    scan3_kernel<<<NB_NODE, 256>>>();
    scatter_kernel<<<NB_EDGE, 256>>>(ei32);

    // conv1 + relu
    agg_kernel<<<NB_AGG, 512>>>(x, mean);
    gemm128_kernel<true><<<NB_G128, 256>>>(mean, x, W1l, W1r, b1, h1);

    // convx
    agg_kernel<<<NB_AGG, 512>>>(h1, mean);
    gemm128_kernel<false><<<NB_G128, 256>>>(mean, h1, Wxl, Wxr, bx, h2);

    // batch_norm3 + relu (in place on h2)
    zero_bn_kernel<<<1, 128>>>();
    bn_stats_kernel<128><<<BN_BLOCKS, 32>>>(h2, ROWS_PER_BLOCK);
    bn_final_kernel<128><<<1, 128>>>(g3, be3);
    {
        long long total = (long long)N_NODES * 128;
        int nb = (int)((total + 255) / 256);
        bn_apply_kernel<128, true><<<nb, 256>>>(h2);
    }

    // conv2
    agg_kernel<<<NB_AGG, 512>>>(h2, mean);
    gemm40_kernel<<<NB_G40, 128>>>(mean, h2, W2l, W2r, b2, out);

    // batch_norm2 (in place on out)
    zero_bn_kernel<<<1, 128>>>();
    bn_stats_kernel<40><<<BN_BLOCKS, 16>>>(out, ROWS_PER_BLOCK);
    bn_final_kernel<40><<<1, 64>>>(g2, be2);
    {
        long long total = (long long)N_NODES * 40;
        int nb = (int)((total + 255) / 256);
        bn_apply_kernel<40, false><<<nb, 256>>>(out);
    }
}